// round 15
// baseline (speedup 1.0000x reference)
#include <cuda_runtime.h>
#include <cuda_fp16.h>
#include <cstdint>

// Problem constants
constexpr int NN   = 50000;
constexpr int DIN  = 128;
constexpr int DOUT = 128;
constexpr int ELLW = 64;

// Scratch
__device__ __half   g_w16[DIN * DOUT];              // fp16 copy of W (32 KB)
__device__ __half   g_hw[(size_t)NN * DOUT];        // fp16 projected features (12.8 MB)
__device__ uint16_t g_ell[(size_t)NN * ELLW];       // packed src ids (6.4 MB)
__device__ int      g_cnt[NN];

// m16n8k16 fp16 mma, f32 accumulate: D += A*B
#define MMA_F16(d, a, b)                                                      \
    asm volatile("mma.sync.aligned.m16n8k16.row.col.f32.f16.f16.f32 "         \
        "{%0,%1,%2,%3}, {%4,%5,%6,%7}, {%8,%9}, {%0,%1,%2,%3};"               \
        : "+f"((d)[0]), "+f"((d)[1]), "+f"((d)[2]), "+f"((d)[3])              \
        : "r"((a)[0]), "r"((a)[1]), "r"((a)[2]), "r"((a)[3]),                 \
          "r"((b)[0]), "r"((b)[1]))

#define LDM_X4(r, addr)                                                       \
    asm volatile("ldmatrix.sync.aligned.m8n8.x4.shared.b16 {%0,%1,%2,%3}, [%4];" \
        : "=r"((r)[0]), "=r"((r)[1]), "=r"((r)[2]), "=r"((r)[3]) : "r"(addr))

#define LDM_X4_T(r, addr)                                                     \
    asm volatile("ldmatrix.sync.aligned.m8n8.x4.trans.shared.b16 {%0,%1,%2,%3}, [%4];" \
        : "=r"((r)[0]), "=r"((r)[1]), "=r"((r)[2]), "=r"((r)[3]) : "r"(addr))

#define CP_ASYNC16(dst, src)                                                  \
    asm volatile("cp.async.ca.shared.global [%0], [%1], 16;"                  \
        :: "r"(dst), "l"(src) : "memory")
#define CP_COMMIT()  asm volatile("cp.async.commit_group;" ::: "memory")
#define CP_WAIT0()   asm volatile("cp.async.wait_group 0;" ::: "memory")

// fp16 tile pitch: 136 halves = 272 B = 17 quads -> conflict-free ldmatrix.
constexpr int PIT   = 136;                      // halves
constexpr int PIT32 = 132;                      // fp32 staging pitch (words)

// SMEM layout (bytes)
constexpr int OFF_A32 = 0;                              // [64 r][132 w] fp32
constexpr int A32_B   = 64 * PIT32 * 4;                 // 33,792
constexpr int OFF_A16 = A32_B;                          // [64 r][136 h] fp16
constexpr int A16_B   = 64 * PIT * 2;                   // 17,408
constexpr int OFF_W16 = OFF_A16 + A16_B;                // [128 k][136 h] fp16 (K-major)
constexpr int W16_B   = 128 * PIT * 2;                  // 34,816
constexpr int SMEM_BYTES = OFF_W16 + W16_B;             // 86,016

// ---------------------------------------------------------------------------
// Kernel 0: prep — convert W to fp16 global, zero g_cnt (tiny).
// ---------------------------------------------------------------------------
__global__ void __launch_bounds__(256) prep_kernel(const float* __restrict__ W)
{
    int i = blockIdx.x * blockDim.x + threadIdx.x;
    if (i < DIN * DOUT / 4) {
        float4 v = *(const float4*)(W + (size_t)i * 4);
        __half hh[4] = {__float2half_rn(v.x), __float2half_rn(v.y),
                        __float2half_rn(v.z), __float2half_rn(v.w)};
        *(uint2*)(g_w16 + (size_t)i * 4) = *(uint2*)hh;
    }
    if (i < NN) g_cnt[i] = 0;
}

// ---------------------------------------------------------------------------
// Kernel 1: hw = fp16((h @ W) * norm), single fp16 mma (f32 accum).
// CTA: 64 rows x 128 cols, 4 warps (warp tile 32x64), full K=128 resident.
// h read as fp32 via cp.async into staging smem, converted in-kernel.
// ---------------------------------------------------------------------------
__global__ void __launch_bounds__(128, 2) gemm_mma_kernel(
    const float* __restrict__ h,
    const float* __restrict__ norm)
{
    extern __shared__ char smem[];
    const uint32_t sb   = (uint32_t)__cvta_generic_to_shared(smem);
    const uint32_t sA32 = sb + OFF_A32;
    const uint32_t sA16 = sb + OFF_A16;
    const uint32_t sW16 = sb + OFF_W16;
    float*  A32 = (float*)(smem + OFF_A32);
    __half* A16 = (__half*)(smem + OFF_A16);

    const int tid  = threadIdx.x;
    const int lane = tid & 31;
    const int wid  = tid >> 5;
    const int wm   = wid & 1;                   // m block (32 rows)
    const int wn   = wid >> 1;                  // n block (64 cols)
    const int g    = lane >> 2;
    const int t    = lane & 3;
    const int row0 = blockIdx.x * 64;

    // ---- async fills: A fp32 (2048 granules), W fp16 (2048 granules) ----
    #pragma unroll
    for (int it = 0; it < 16; it++) {
        int i  = it * 128 + tid;
        int r  = i >> 5;                         // 0..63
        int c4 = (i & 31) << 2;                  // float offset (16B granule)
        int gr = row0 + r;
        if (gr >= NN) gr = NN - 1;               // clamp (stores guarded later)
        CP_ASYNC16(sA32 + (uint32_t)(r * PIT32 + c4) * 4,
                   h + (size_t)gr * DIN + c4);
    }
    #pragma unroll
    for (int it = 0; it < 16; it++) {
        int i  = it * 128 + tid;
        int k  = i >> 4;                         // 0..127
        int gq = (i & 15) << 3;                  // half offset
        CP_ASYNC16(sW16 + (uint32_t)(k * PIT + gq) * 2,
                   g_w16 + (size_t)k * DOUT + gq);
    }
    CP_COMMIT();
    CP_WAIT0();
    __syncthreads();

    // ---- convert A fp32 -> fp16 tile (LDS.128 -> cvt -> STS.64) ----
    #pragma unroll
    for (int it = 0; it < 16; it++) {
        int i  = it * 128 + tid;
        int r  = i >> 5;                         // 0..63
        int c4 = (i & 31) << 2;                  // 0..124
        float4 v = *(const float4*)(A32 + r * PIT32 + c4);
        __half2 p0 = __floats2half2_rn(v.x, v.y);
        __half2 p1 = __floats2half2_rn(v.z, v.w);
        __half2* dst2 = (__half2*)(A16 + r * PIT + c4);
        dst2[0] = p0;
        dst2[1] = p1;
    }
    __syncthreads();

    // ldmatrix base addresses (bytes, shared space)
    const uint32_t adrA = sA16 + (uint32_t)(((wm * 32 + (lane & 15)) * PIT
                                             + ((lane >> 4) << 3)) * 2);
    const uint32_t adrB = sW16 + (uint32_t)(((lane & 15) * PIT
                                             + wn * 64 + ((lane >> 4) << 3)) * 2);

    float acc[2][8][4];
    #pragma unroll
    for (int mt = 0; mt < 2; mt++)
        #pragma unroll
        for (int nt = 0; nt < 8; nt++)
            #pragma unroll
            for (int e = 0; e < 4; e++)
                acc[mt][nt][e] = 0.f;

    // ---- 8 k-steps of 16 over full K=128 ----
    #pragma unroll
    for (int ks = 0; ks < 8; ks++) {
        const uint32_t akb = (uint32_t)(ks * 16 * 2);          // A: +16 halves in k
        const uint32_t bkb = (uint32_t)(ks * 16 * PIT * 2);    // B: +16 rows in k

        uint32_t ah[2][4];
        #pragma unroll
        for (int mt = 0; mt < 2; mt++)
            LDM_X4(ah[mt], adrA + (uint32_t)(mt * 16 * PIT * 2) + akb);

        #pragma unroll
        for (int np = 0; np < 4; np++) {
            uint32_t bv[4];
            LDM_X4_T(bv, adrB + (uint32_t)(np * 16 * 2) + bkb);
            #pragma unroll
            for (int half = 0; half < 2; half++) {
                int nt = 2 * np + half;
                uint32_t b[2] = {bv[2 * half], bv[2 * half + 1]};
                #pragma unroll
                for (int mt = 0; mt < 2; mt++)
                    MMA_F16(acc[mt][nt], ah[mt], b);
            }
        }
    }

    // ---- epilogue: scale by norm[row], convert to fp16, store g_hw ----
    #pragma unroll
    for (int mt = 0; mt < 2; mt++) {
        int r_lo = row0 + wm * 32 + mt * 16 + g;
        int r_hi = r_lo + 8;
        float n_lo = (r_lo < NN) ? __ldg(norm + r_lo) : 0.f;
        float n_hi = (r_hi < NN) ? __ldg(norm + r_hi) : 0.f;
        #pragma unroll
        for (int nt = 0; nt < 8; nt++) {
            int col = wn * 64 + nt * 8 + 2 * t;
            if (r_lo < NN) {
                __half2 o = __floats2half2_rn(acc[mt][nt][0] * n_lo,
                                              acc[mt][nt][1] * n_lo);
                *(__half2*)(g_hw + (size_t)r_lo * DOUT + col) = o;
            }
            if (r_hi < NN) {
                __half2 o = __floats2half2_rn(acc[mt][nt][2] * n_hi,
                                              acc[mt][nt][3] * n_hi);
                *(__half2*)(g_hw + (size_t)r_hi * DOUT + col) = o;
            }
        }
    }
}

// ---------------------------------------------------------------------------
// Kernel 2: build ELL adjacency (u16 ids). Two edges per thread (int2 loads,
// 2 independent atomic chains for ILP).
// ---------------------------------------------------------------------------
__global__ void __launch_bounds__(256) build_kernel(
    const int* __restrict__ src,
    const int* __restrict__ dst,
    float* __restrict__ out,
    int E)
{
    int p = blockIdx.x * blockDim.x + threadIdx.x;   // pair index
    int e0 = p * 2;
    if (e0 >= E) return;

    if (e0 + 1 < E) {
        int2 s2 = *(const int2*)(src + e0);
        int2 d2 = *(const int2*)(dst + e0);
        int pos0 = atomicAdd(&g_cnt[d2.x], 1);
        int pos1 = atomicAdd(&g_cnt[d2.y], 1);
        if (pos0 < ELLW) g_ell[(size_t)d2.x * ELLW + pos0] = (uint16_t)s2.x;
        if (pos1 < ELLW) g_ell[(size_t)d2.y * ELLW + pos1] = (uint16_t)s2.y;
        // deg > 64: P ~ 1e-13 (Poisson(16)); overflow fallback handled below
        if (pos0 >= ELLW || pos1 >= ELLW) {
            for (int q = 0; q < 2; q++) {
                int pos = q ? pos1 : pos0;
                if (pos < ELLW) continue;
                int s = q ? s2.y : s2.x;
                int d = q ? d2.y : d2.x;
                const __half* hs = g_hw + (size_t)s * DOUT;
                float* po = out + (size_t)d * DOUT;
                for (int j = 0; j < DOUT; j += 2) {
                    float2 v = __half22float2(*(const __half2*)(hs + j));
                    asm volatile("red.global.add.f32 [%0], %1;" :: "l"(po + j),     "f"(v.x) : "memory");
                    asm volatile("red.global.add.f32 [%0], %1;" :: "l"(po + j + 1), "f"(v.y) : "memory");
                }
            }
        }
    } else {
        int s = __ldg(src + e0);
        int d = __ldg(dst + e0);
        int pos = atomicAdd(&g_cnt[d], 1);
        if (pos < ELLW) g_ell[(size_t)d * ELLW + pos] = (uint16_t)s;
    }
}

// ---------------------------------------------------------------------------
// Kernel 3: aggregate + fused epilogue. One warp per dst node.
// 8 rows per iteration as two independent depth-2 fp16 trees (bit-identical
// summation order vs 4-row version), fp32 master accumulator.
// ---------------------------------------------------------------------------
__global__ void __launch_bounds__(256) agg_kernel(
    float* __restrict__ out,
    const float* __restrict__ norm,
    const float* __restrict__ bias)
{
    int warp = (blockIdx.x * blockDim.x + threadIdx.x) >> 5;
    int lane = threadIdx.x & 31;
    if (warp >= NN) return;
    const int d = warp;

    int cnt_raw = __ldg(&g_cnt[d]);
    int n = cnt_raw < ELLW ? cnt_raw : ELLW;

    // lane i holds packed ids for slots 2i, 2i+1
    uint32_t packed = *(const uint32_t*)(g_ell + (size_t)d * ELLW + 2 * lane);

    float4 acc = make_float4(0.f, 0.f, 0.f, 0.f);
    const int co = lane * 4;

    int i = 0;
    // 8 rows per iteration: 8 batched loads, two depth-2 trees
    for (; i + 8 <= n; i += 8) {
        uint32_t p0 = __shfl_sync(0xffffffffu, packed, (i >> 1) + 0);
        uint32_t p1 = __shfl_sync(0xffffffffu, packed, (i >> 1) + 1);
        uint32_t p2 = __shfl_sync(0xffffffffu, packed, (i >> 1) + 2);
        uint32_t p3 = __shfl_sync(0xffffffffu, packed, (i >> 1) + 3);
        int s0 = (int)(p0 & 0xffffu), s1 = (int)(p0 >> 16);
        int s2 = (int)(p1 & 0xffffu), s3 = (int)(p1 >> 16);
        int s4 = (int)(p2 & 0xffffu), s5 = (int)(p2 >> 16);
        int s6 = (int)(p3 & 0xffffu), s7 = (int)(p3 >> 16);

        uint2 u0 = *(const uint2*)(g_hw + (size_t)s0 * DOUT + co);
        uint2 u1 = *(const uint2*)(g_hw + (size_t)s1 * DOUT + co);
        uint2 u2 = *(const uint2*)(g_hw + (size_t)s2 * DOUT + co);
        uint2 u3 = *(const uint2*)(g_hw + (size_t)s3 * DOUT + co);
        uint2 u4 = *(const uint2*)(g_hw + (size_t)s4 * DOUT + co);
        uint2 u5 = *(const uint2*)(g_hw + (size_t)s5 * DOUT + co);
        uint2 u6 = *(const uint2*)(g_hw + (size_t)s6 * DOUT + co);
        uint2 u7 = *(const uint2*)(g_hw + (size_t)s7 * DOUT + co);

        // tree A (rows 0-3)
        __half2 xa = __hadd2(__hadd2(*(__half2*)&u0.x, *(__half2*)&u1.x),
                             __hadd2(*(__half2*)&u2.x, *(__half2*)&u3.x));
        __half2 ya = __hadd2(__hadd2(*(__half2*)&u0.y, *(__half2*)&u1.y),
                             __hadd2(*(__half2*)&u2.y, *(__half2*)&u3.y));
        float2 fxa = __half22float2(xa);
        float2 fya = __half22float2(ya);
        acc.x += fxa.x; acc.y += fxa.y; acc.z += fya.x; acc.w += fya.y;

        // tree B (rows 4-7)
        __half2 xb = __hadd2(__hadd2(*(__half2*)&u4.x, *(__half2*)&u5.x),
                             __hadd2(*(__half2*)&u6.x, *(__half2*)&u7.x));
        __half2 yb = __hadd2(__hadd2(*(__half2*)&u4.y, *(__half2*)&u5.y),
                             __hadd2(*(__half2*)&u6.y, *(__half2*)&u7.y));
        float2 fxb = __half22float2(xb);
        float2 fyb = __half22float2(yb);
        acc.x += fxb.x; acc.y += fxb.y; acc.z += fyb.x; acc.w += fyb.y;
    }
    // 4-row iterations
    for (; i + 4 <= n; i += 4) {
        uint32_t p0 = __shfl_sync(0xffffffffu, packed, i >> 1);
        uint32_t p1 = __shfl_sync(0xffffffffu, packed, (i >> 1) + 1);
        int s0 = (int)(p0 & 0xffffu), s1 = (int)(p0 >> 16);
        int s2 = (int)(p1 & 0xffffu), s3 = (int)(p1 >> 16);

        uint2 u0 = *(const uint2*)(g_hw + (size_t)s0 * DOUT + co);
        uint2 u1 = *(const uint2*)(g_hw + (size_t)s1 * DOUT + co);
        uint2 u2 = *(const uint2*)(g_hw + (size_t)s2 * DOUT + co);
        uint2 u3 = *(const uint2*)(g_hw + (size_t)s3 * DOUT + co);

        __half2 xs = __hadd2(__hadd2(*(__half2*)&u0.x, *(__half2*)&u1.x),
                             __hadd2(*(__half2*)&u2.x, *(__half2*)&u3.x));
        __half2 ys = __hadd2(__hadd2(*(__half2*)&u0.y, *(__half2*)&u1.y),
                             __hadd2(*(__half2*)&u2.y, *(__half2*)&u3.y));
        float2 fx = __half22float2(xs);
        float2 fy = __half22float2(ys);
        acc.x += fx.x; acc.y += fx.y; acc.z += fy.x; acc.w += fy.y;
    }
    // remainder: exact fp32 path
    for (; i < n; i++) {
        uint32_t p = __shfl_sync(0xffffffffu, packed, i >> 1);
        int s0 = (int)((i & 1) ? (p >> 16) : (p & 0xffffu));
        uint2 u = *(const uint2*)(g_hw + (size_t)s0 * DOUT + co);
        float2 a = __half22float2(*(__half2*)&u.x);
        float2 b = __half22float2(*(__half2*)&u.y);
        acc.x += a.x; acc.y += a.y; acc.z += b.x; acc.w += b.y;
    }

    if (cnt_raw > ELLW) {   // never in practice
        float4 ov = *(const float4*)(out + (size_t)d * DOUT + co);
        acc.x += ov.x; acc.y += ov.y; acc.z += ov.z; acc.w += ov.w;
    }

    float nr = __ldg(norm + d);
    float4 b = *(const float4*)(bias + co);
    float4 r;
    r.x = fmaxf(fmaf(acc.x, nr, b.x), 0.f);
    r.y = fmaxf(fmaf(acc.y, nr, b.y), 0.f);
    r.z = fmaxf(fmaf(acc.z, nr, b.z), 0.f);
    r.w = fmaxf(fmaf(acc.w, nr, b.w), 0.f);
    *(float4*)(out + (size_t)d * DOUT + co) = r;
}

// ---------------------------------------------------------------------------
// Launch. Input order (metadata): h, weight, bias, norm, src, dst
// ---------------------------------------------------------------------------
extern "C" void kernel_launch(void* const* d_in, const int* in_sizes, int n_in,
                              void* d_out, int out_size)
{
    const float* h    = (const float*)d_in[0];
    const float* W    = (const float*)d_in[1];
    const float* bias = (const float*)d_in[2];
    const float* norm = (const float*)d_in[3];
    const int*   src  = (const int*)d_in[4];
    const int*   dst  = (const int*)d_in[5];
    float*       out  = (float*)d_out;

    const int E = in_sizes[4];

    cudaFuncSetAttribute(gemm_mma_kernel,
                         cudaFuncAttributeMaxDynamicSharedMemorySize, SMEM_BYTES);

    // 0) convert W to fp16; zero g_cnt (tiny)
    prep_kernel<<<(NN + 255) / 256, 256>>>(W);

    // 1) projection -> fp16 g_hw (cp.async fp32 h + in-smem convert + fp16 mma)
    gemm_mma_kernel<<<(NN + 63) / 64, 128, SMEM_BYTES>>>(h, norm);

    // 2) build per-dst adjacency (ELL, u16), 2 edges/thread
    {
        int pairs = (E + 1) / 2;
        build_kernel<<<(pairs + 255) / 256, 256>>>(src, dst, out, E);
    }

    // 3) gather-aggregate + fused norm/bias/relu (one warp per node)
    agg_kernel<<<(NN * 32 + 255) / 256, 256>>>(out, norm, bias);
}